// round 6
// baseline (speedup 1.0000x reference)
#include <cuda_runtime.h>
#include <math.h>

#define BB 32
#define DIM 4096
#define NH 32
#define NKV 8
#define GQ 4
#define HD 128
#define KVLEN 4096
#define QKVC 6144          // (NH + 2*NKV) * HD
#define KSPLIT 16          // K-dim split for GEMMs
#define KCH 256            // K chunk per block (DIM / KSPLIT)
#define CHUNK 256          // KV positions per attention split
#define NSPLIT 16          // KVLEN / CHUNK

// packed fp32x2 FMA (sm_100+): 2x FLOP per issue slot vs FFMA
#define FMA_F32X2(d, a, b, c) \
    asm("fma.rn.f32x2 %0, %1, %2, %3;" : "=l"(d) : "l"(a), "l"(b), "l"(c))

// ---------------- scratch (no allocs allowed) ----------------
__device__ float g_part1[KSPLIT][BB][QKVC];     // qkv gemm partials
__device__ float g_part2[KSPLIT][BB][DIM];      // out gemm partials
__device__ float g_q[BB * NH * HD];             // rope'd q
__device__ float g_knew[BB * NKV * HD];         // rope'd new k
__device__ float g_vnew[BB * NKV * HD];         // new v
__device__ float g_pm[BB * NKV * NSPLIT * GQ];  // partial max
__device__ float g_ps[BB * NKV * NSPLIT * GQ];  // partial sumexp
__device__ float g_pacc[BB * NKV * NSPLIT * GQ * HD]; // partial weighted V
__device__ float g_attn[BB * DIM];              // attention output (pre-wo)

// ---------------- GEMM partial: f32x2 FMA + depth-8 weight prefetch ----------------
template <int COLS>
__global__ void __launch_bounds__(256) k_gemm_part(const float* __restrict__ x,
                                                   const float* __restrict__ w,
                                                   float* __restrict__ part) {
    __shared__ float xs[KCH][BB];  // transposed x tile, 32 KB
    const int c = blockIdx.x * 256 + threadIdx.x;
    const int d0 = blockIdx.y * KCH;
    for (int i = threadIdx.x; i < KCH * BB; i += 256) {
        int dd = i >> 5, b = i & 31;
        xs[dd][b] = x[b * DIM + d0 + dd];
    }
    __syncthreads();
    unsigned long long acc[16];  // 16 f32x2 pairs = 32 batch accumulators
#pragma unroll
    for (int i = 0; i < 16; i++) acc[i] = 0ull;

    const float* wcol = w + (size_t)d0 * COLS + c;
    float wv[8];
#pragma unroll
    for (int u = 0; u < 8; u++) wv[u] = wcol[(size_t)u * COLS];  // MLP=8 prime

    for (int g = 0; g < KCH; g += 8) {
        float wn[8];
        if (g + 8 < KCH) {
            const float* wnp = wcol + (size_t)(g + 8) * COLS;
#pragma unroll
            for (int u = 0; u < 8; u++) wn[u] = wnp[(size_t)u * COLS];  // 8 in flight
        } else {
#pragma unroll
            for (int u = 0; u < 8; u++) wn[u] = 0.f;
        }
#pragma unroll
        for (int u = 0; u < 8; u++) {
            unsigned long long w2;
            asm("mov.b64 %0, {%1, %1};" : "=l"(w2) : "f"(wv[u]));
            const ulonglong2* xr = (const ulonglong2*)xs[g + u];
#pragma unroll
            for (int j = 0; j < 8; j++) {
                ulonglong2 xv = xr[j];  // LDS.128 broadcast: 4 batches
                FMA_F32X2(acc[2 * j + 0], xv.x, w2, acc[2 * j + 0]);
                FMA_F32X2(acc[2 * j + 1], xv.y, w2, acc[2 * j + 1]);
            }
        }
#pragma unroll
        for (int u = 0; u < 8; u++) wv[u] = wn[u];
    }

    float* o = part + (size_t)blockIdx.y * BB * COLS + c;
#pragma unroll
    for (int i = 0; i < 16; i++) {
        float lo, hi;
        asm("mov.b64 {%0, %1}, %2;" : "=f"(lo), "=f"(hi) : "l"(acc[i]));
        o[(size_t)(2 * i) * COLS] = lo;
        o[(size_t)(2 * i + 1) * COLS] = hi;
    }
}

// ---------------- reduce qkv partials + rope ----------------
__global__ void __launch_bounds__(128) k_reduce_rope(const float* __restrict__ rot) {
    const int b = blockIdx.x / 48;
    const int h = blockIdx.x % 48;
    const int t = threadIdx.x;
    float s = 0.f;
#pragma unroll
    for (int p = 0; p < KSPLIT; p++) s += g_part1[p][b][h * HD + t];
    if (h >= 40) {  // v: no rope (uniform per block)
        g_vnew[(b * NKV + (h - 40)) * HD + t] = s;
        return;
    }
    __shared__ float vsh[HD];
    vsh[t] = s;
    __syncthreads();
    float o = 0.f;
#pragma unroll 8
    for (int d = 0; d < HD; d++) o = fmaf(vsh[d], rot[d * HD + t], o);
    if (h < 32)
        g_q[(b * NH + h) * HD + t] = o;
    else
        g_knew[(b * NKV + (h - 32)) * HD + t] = o;
}

// ---------------- dummy: keeps k_attn_part in the ncu-profiled launch slot ----
__global__ void k_dummy() {}

// ---------------- flash-decode partial attention (256 threads) ----------------
// grid (BB*NKV, NSPLIT). Score: 1 thread per KV row, FFMA2 + depth-4 prefetch.
// V: 2-way s-split, FFMA2. Splits beyond L exit with no writes.
__global__ void __launch_bounds__(256) k_attn_part(const float* __restrict__ ck,
                                                   const float* __restrict__ cv,
                                                   const int* __restrict__ curp) {
    const int bk = blockIdx.x;  // b*NKV + kv
    const int b = bk >> 3, kv = bk & 7;
    const int sp = blockIdx.y;
    const int cur = *curp;
    const int L = cur + 1;
    const int s0 = sp * CHUNK;
    const int scnt = min(CHUNK, L - s0);
    if (scnt <= 0) return;
    const int pbase = (bk * NSPLIT + sp) * GQ;
    const int t = threadIdx.x;
    const bool has_cur = (s0 + CHUNK >= L);  // cur at s = scnt-1 of last split

    __shared__ float4 sc4[CHUNK];        // probs, transposed: sc4[s]={h0..h3}
    __shared__ float4 qsh[GQ][HD / 4];
    __shared__ float red[8];
    __shared__ float mh[GQ], sumh[GQ];
    __shared__ float vred[GQ][HD];       // V-stage cross-half reduce

    ((float2*)qsh)[t] = ((const float2*)(g_q + (b * NH + kv * GQ) * HD))[t];
    __syncthreads();

    const float scale = 0.08838834764831845f;  // 1/sqrt(128)
    // ---- scores: one KV row per thread, FFMA2 + depth-4 prefetch ----
    if (t < scnt) {
        const int s = t;
        const ulonglong2* kr = (has_cur && s == scnt - 1)
            ? (const ulonglong2*)(g_knew + (b * NKV + kv) * HD)
            : (const ulonglong2*)(ck + ((size_t)(b * NKV + kv) * KVLEN + s0 + s) * HD);
        ulonglong2 kb[4];
#pragma unroll
        for (int u = 0; u < 4; u++) kb[u] = kr[u];
        unsigned long long acc[4] = {0ull, 0ull, 0ull, 0ull};
#pragma unroll
        for (int j0 = 0; j0 < 32; j0 += 4) {
            ulonglong2 kn[4];
            if (j0 < 28) {
#pragma unroll
                for (int u = 0; u < 4; u++) kn[u] = kr[j0 + 4 + u];  // 4 in flight
            }
#pragma unroll
            for (int u = 0; u < 4; u++) {
#pragma unroll
                for (int h = 0; h < 4; h++) {
                    ulonglong2 q2 = ((const ulonglong2*)qsh[h])[j0 + u];  // LDS.128
                    FMA_F32X2(acc[h], kb[u].x, q2.x, acc[h]);
                    FMA_F32X2(acc[h], kb[u].y, q2.y, acc[h]);
                }
            }
#pragma unroll
            for (int u = 0; u < 4; u++) kb[u] = kn[u];
        }
        float r[4];
#pragma unroll
        for (int h = 0; h < 4; h++) {
            float lo, hi;
            asm("mov.b64 {%0, %1}, %2;" : "=f"(lo), "=f"(hi) : "l"(acc[h]));
            r[h] = (lo + hi) * scale;
        }
        sc4[s] = make_float4(r[0], r[1], r[2], r[3]);
    }
    __syncthreads();

    // ---- softmax, 4 heads in parallel: 64 threads per head ----
    {
        const int h = t >> 6, l64 = t & 63, wid = t >> 5, lane = t & 31;
        const float* schf = (const float*)sc4;  // schf[s*4 + h]
        float lm = -INFINITY;
        for (int s = l64; s < scnt; s += 64) lm = fmaxf(lm, schf[s * 4 + h]);
#pragma unroll
        for (int o = 16; o > 0; o >>= 1) lm = fmaxf(lm, __shfl_xor_sync(0xffffffffu, lm, o));
        if (lane == 0) red[wid] = lm;
        __syncthreads();
        if (l64 == 0) mh[h] = fmaxf(red[2 * h], red[2 * h + 1]);
        __syncthreads();
        const float m = mh[h];
        float ls = 0.f;
        float* scw = (float*)sc4;
        for (int s = l64; s < scnt; s += 64) {
            float p = __expf(scw[s * 4 + h] - m);
            scw[s * 4 + h] = p;
            ls += p;
        }
#pragma unroll
        for (int o = 16; o > 0; o >>= 1) ls += __shfl_xor_sync(0xffffffffu, ls, o);
        if (lane == 0) red[wid] = ls;
        __syncthreads();
        if (l64 == 0) sumh[h] = red[2 * h] + red[2 * h + 1];
    }
    __syncthreads();

    // ---- p @ V: d = t&127, s over 2 halves; f32x2 FMA ----
    {
        const int d = t & 127, half = t >> 7;
        unsigned long long a01 = 0ull, a23 = 0ull;
        const float* vbase = cv + ((size_t)(b * NKV + kv) * KVLEN + s0) * HD + d;
        const int slim = scnt - (has_cur ? 1 : 0);
#pragma unroll 8
        for (int s = half; s < slim; s += 2) {
            float vv = vbase[(size_t)s * HD];
            ulonglong2 p = ((const ulonglong2*)sc4)[s];  // broadcast LDS.128
            unsigned long long v2;
            asm("mov.b64 %0, {%1, %1};" : "=l"(v2) : "f"(vv));
            FMA_F32X2(a01, p.x, v2, a01);
            FMA_F32X2(a23, p.y, v2, a23);
        }
        if (has_cur && ((scnt - 1) & 1) == half) {
            const int s = scnt - 1;
            float vv = g_vnew[(b * NKV + kv) * HD + d];
            ulonglong2 p = ((const ulonglong2*)sc4)[s];
            unsigned long long v2;
            asm("mov.b64 %0, {%1, %1};" : "=l"(v2) : "f"(vv));
            FMA_F32X2(a01, p.x, v2, a01);
            FMA_F32X2(a23, p.y, v2, a23);
        }
        float a0, a1, a2, a3;
        asm("mov.b64 {%0, %1}, %2;" : "=f"(a0), "=f"(a1) : "l"(a01));
        asm("mov.b64 {%0, %1}, %2;" : "=f"(a2), "=f"(a3) : "l"(a23));
        if (half == 1) {
            vred[0][d] = a0; vred[1][d] = a1; vred[2][d] = a2; vred[3][d] = a3;
        }
        __syncthreads();
        if (half == 0) {
            g_pacc[(pbase + 0) * HD + d] = a0 + vred[0][d];
            g_pacc[(pbase + 1) * HD + d] = a1 + vred[1][d];
            g_pacc[(pbase + 2) * HD + d] = a2 + vred[2][d];
            g_pacc[(pbase + 3) * HD + d] = a3 + vred[3][d];
        }
        if (t < GQ) {
            g_pm[pbase + t] = mh[t];
            g_ps[pbase + t] = sumh[t];
        }
    }
}

// ---------------- LSE merge across splits (length-aware, float4) ----------------
__global__ void __launch_bounds__(128) k_combine(const int* __restrict__ curp) {
    const int bk = blockIdx.x;
    const int b = bk >> 3, kv = bk & 7;
    const int t = threadIdx.x;
    const int h = t >> 5, d4 = t & 31;
    const int nsp = (*curp + CHUNK) / CHUNK;  // ceil(L/CHUNK)

    __shared__ float esh[GQ][NSPLIT];
    __shared__ float dens[GQ];
    if (d4 == 0) {
        float m = -INFINITY;
        for (int sp = 0; sp < nsp; sp++)
            m = fmaxf(m, g_pm[(bk * NSPLIT + sp) * GQ + h]);
        float den = 0.f;
        for (int sp = 0; sp < nsp; sp++) {
            float e = __expf(g_pm[(bk * NSPLIT + sp) * GQ + h] - m);
            esh[h][sp] = e;
            den += g_ps[(bk * NSPLIT + sp) * GQ + h] * e;
        }
        dens[h] = den;
    }
    __syncthreads();
    float4 num = make_float4(0.f, 0.f, 0.f, 0.f);
#pragma unroll 4
    for (int sp = 0; sp < nsp; sp++) {
        const float4* pa = (const float4*)(g_pacc + ((bk * NSPLIT + sp) * GQ + h) * HD);
        float4 v = pa[d4];
        float e = esh[h][sp];
        num.x = fmaf(v.x, e, num.x); num.y = fmaf(v.y, e, num.y);
        num.z = fmaf(v.z, e, num.z); num.w = fmaf(v.w, e, num.w);
    }
    const float inv = 1.0f / dens[h];
    float4* o = (float4*)(g_attn + (b * NH + kv * GQ + h) * HD);
    o[d4] = make_float4(num.x * inv, num.y * inv, num.z * inv, num.w * inv);
}

// ---------------- final reduce of out-gemm partials (float4) ----------------
__global__ void __launch_bounds__(256) k_out_reduce(float* __restrict__ out) {
    const int i = blockIdx.x * 256 + threadIdx.x;  // float4 index
    const float4* p2 = (const float4*)g_part2;
    float4 s = make_float4(0.f, 0.f, 0.f, 0.f);
#pragma unroll
    for (int p = 0; p < KSPLIT; p++) {
        float4 v = p2[(size_t)p * (BB * DIM / 4) + i];
        s.x += v.x; s.y += v.y; s.z += v.z; s.w += v.w;
    }
    ((float4*)out)[i] = s;
}

extern "C" void kernel_launch(void* const* d_in, const int* in_sizes, int n_in,
                              void* d_out, int out_size) {
    const float* x    = (const float*)d_in[0];  // attn_norm (1,1,32,4096)
    const float* wqkv = (const float*)d_in[1];  // (4096, 6144)
    const float* wo   = (const float*)d_in[2];  // (4096, 4096)
    const float* rot  = (const float*)d_in[3];  // (128, 128)
    const float* ck   = (const float*)d_in[4];  // (32,8,4096,128)
    const float* cv   = (const float*)d_in[5];  // (32,8,4096,128)
    const int*   curp = (const int*)d_in[6];    // current_pos (low 32 bits)
    float* out = (float*)d_out;

    void *p1, *p2, *attnp;
    cudaGetSymbolAddress(&p1, g_part1);
    cudaGetSymbolAddress(&p2, g_part2);
    cudaGetSymbolAddress(&attnp, g_attn);

    k_gemm_part<QKVC><<<dim3(QKVC / 256, KSPLIT), 256>>>(x, wqkv, (float*)p1);
    k_reduce_rope<<<BB * 48, 128>>>(rot);
    k_dummy<<<1, 32>>>();  // keep k_attn_part in profiled launch slot
    k_attn_part<<<dim3(BB * NKV, NSPLIT), 256>>>(ck, cv, curp);
    k_combine<<<BB * NKV, 128>>>(curp);
    k_gemm_part<DIM><<<dim3(DIM / 256, KSPLIT), 256>>>((const float*)attnp, wo, (float*)p2);
    k_out_reduce<<<BB * DIM / 4 / 256, 256>>>(out);
}

// round 7
// speedup vs baseline: 1.1595x; 1.1595x over previous
#include <cuda_runtime.h>
#include <math.h>

#define BB 32
#define DIM 4096
#define NH 32
#define NKV 8
#define GQ 4
#define HD 128
#define KVLEN 4096
#define QKVC 6144          // (NH + 2*NKV) * HD
#define KSPLIT 16          // K-dim split for GEMMs
#define KCH 256            // K chunk per block (DIM / KSPLIT)
#define CHUNK 256          // KV positions per attention split
#define NSPLIT 16          // KVLEN / CHUNK

// packed fp32x2 FMA (sm_100+): 2x FLOP per issue slot vs FFMA
#define FMA_F32X2(d, a, b, c) \
    asm("fma.rn.f32x2 %0, %1, %2, %3;" : "=l"(d) : "l"(a), "l"(b), "l"(c))

// ---------------- scratch (no allocs allowed) ----------------
__device__ float g_part1[KSPLIT][BB][QKVC];     // qkv gemm partials
__device__ float g_part2[KSPLIT][BB][DIM];      // out gemm partials
__device__ float g_q[BB * NH * HD];             // rope'd q
__device__ float g_knew[BB * NKV * HD];         // rope'd new k
__device__ float g_vnew[BB * NKV * HD];         // new v
__device__ float g_pm[BB * NKV * NSPLIT * GQ];  // partial max
__device__ float g_ps[BB * NKV * NSPLIT * GQ];  // partial sumexp
__device__ float g_pacc[BB * NKV * NSPLIT * GQ * HD]; // partial weighted V
__device__ float g_attn[BB * DIM];              // attention output (pre-wo)

// ---------------- GEMM partial: f32x2 FMA + depth-8 weight prefetch ----------------
template <int COLS>
__global__ void __launch_bounds__(256) k_gemm_part(const float* __restrict__ x,
                                                   const float* __restrict__ w,
                                                   float* __restrict__ part) {
    __shared__ float xs[KCH][BB];  // transposed x tile, 32 KB
    const int c = blockIdx.x * 256 + threadIdx.x;
    const int d0 = blockIdx.y * KCH;
    for (int i = threadIdx.x; i < KCH * BB; i += 256) {
        int dd = i >> 5, b = i & 31;
        xs[dd][b] = x[b * DIM + d0 + dd];
    }
    __syncthreads();
    unsigned long long acc[16];  // 16 f32x2 pairs = 32 batch accumulators
#pragma unroll
    for (int i = 0; i < 16; i++) acc[i] = 0ull;

    const float* wcol = w + (size_t)d0 * COLS + c;
    float wv[8];
#pragma unroll
    for (int u = 0; u < 8; u++) wv[u] = wcol[(size_t)u * COLS];  // MLP=8 prime

    for (int g = 0; g < KCH; g += 8) {
        float wn[8];
        if (g + 8 < KCH) {
            const float* wnp = wcol + (size_t)(g + 8) * COLS;
#pragma unroll
            for (int u = 0; u < 8; u++) wn[u] = wnp[(size_t)u * COLS];  // 8 in flight
        } else {
#pragma unroll
            for (int u = 0; u < 8; u++) wn[u] = 0.f;
        }
#pragma unroll
        for (int u = 0; u < 8; u++) {
            unsigned long long w2;
            asm("mov.b64 %0, {%1, %1};" : "=l"(w2) : "f"(wv[u]));
            const ulonglong2* xr = (const ulonglong2*)xs[g + u];
#pragma unroll
            for (int j = 0; j < 8; j++) {
                ulonglong2 xv = xr[j];  // LDS.128 broadcast: 4 batches
                FMA_F32X2(acc[2 * j + 0], xv.x, w2, acc[2 * j + 0]);
                FMA_F32X2(acc[2 * j + 1], xv.y, w2, acc[2 * j + 1]);
            }
        }
#pragma unroll
        for (int u = 0; u < 8; u++) wv[u] = wn[u];
    }

    float* o = part + (size_t)blockIdx.y * BB * COLS + c;
#pragma unroll
    for (int i = 0; i < 16; i++) {
        float lo, hi;
        asm("mov.b64 {%0, %1}, %2;" : "=f"(lo), "=f"(hi) : "l"(acc[i]));
        o[(size_t)(2 * i) * COLS] = lo;
        o[(size_t)(2 * i + 1) * COLS] = hi;
    }
}

// ---------------- reduce qkv partials + rope ----------------
__global__ void __launch_bounds__(128) k_reduce_rope(const float* __restrict__ rot) {
    const int b = blockIdx.x / 48;
    const int h = blockIdx.x % 48;
    const int t = threadIdx.x;
    float s = 0.f;
#pragma unroll
    for (int p = 0; p < KSPLIT; p++) s += g_part1[p][b][h * HD + t];
    if (h >= 40) {  // v: no rope (uniform per block)
        g_vnew[(b * NKV + (h - 40)) * HD + t] = s;
        return;
    }
    __shared__ float vsh[HD];
    vsh[t] = s;
    __syncthreads();
    float o = 0.f;
#pragma unroll 8
    for (int d = 0; d < HD; d++) o = fmaf(vsh[d], rot[d * HD + t], o);
    if (h < 32)
        g_q[(b * NH + h) * HD + t] = o;
    else
        g_knew[(b * NKV + (h - 32)) * HD + t] = o;
}

// ---------------- dummy: keeps k_attn_part in the ncu-profiled launch slot ----
__global__ void k_dummy() {}

// ---------------- flash-decode partial attention (256 threads) ----------------
// grid (BB*NKV, NSPLIT). Score: COALESCED — 8 lanes per KV row, 4 rows per
// warp; every LDG.128 covers 4 full 128B lines, fully consumed. V: 2-way
// s-split, FFMA2. Splits beyond L exit with no writes.
__global__ void __launch_bounds__(256) k_attn_part(const float* __restrict__ ck,
                                                   const float* __restrict__ cv,
                                                   const int* __restrict__ curp) {
    const int bk = blockIdx.x;  // b*NKV + kv
    const int b = bk >> 3, kv = bk & 7;
    const int sp = blockIdx.y;
    const int cur = *curp;
    const int L = cur + 1;
    const int s0 = sp * CHUNK;
    const int scnt = min(CHUNK, L - s0);
    if (scnt <= 0) return;
    const int pbase = (bk * NSPLIT + sp) * GQ;
    const int t = threadIdx.x;
    const bool has_cur = (s0 + CHUNK >= L);  // cur at s = scnt-1 of last split

    __shared__ float4 sc4[CHUNK];        // probs, transposed: sc4[s]={h0..h3}
    __shared__ float4 qsh[GQ][HD / 4];
    __shared__ float red[8];
    __shared__ float mh[GQ], sumh[GQ];
    __shared__ float vred[GQ][HD];       // V-stage cross-half reduce

    ((float2*)qsh)[t] = ((const float2*)(g_q + (b * NH + kv * GQ) * HD))[t];
    __syncthreads();

    const float scale = 0.08838834764831845f;  // 1/sqrt(128)
    const float* kbase = ck + (size_t)(b * NKV + kv) * KVLEN * HD;

    // ---- scores: warp covers 4 rows, 8 lanes per row (coalesced LDG.128) ----
    {
        const int lane = t & 31, w = t >> 5;
        const int d8 = lane & 7;   // float4 column slot within row
        const int r4 = lane >> 3;  // row within the 4-row group
        for (int g = w; g < CHUNK / 4; g += 8) {
            const int s = g * 4 + r4;
            const bool act = (s < scnt);
            ulonglong2 k4[4];
#pragma unroll
            for (int j = 0; j < 4; j++) { k4[j].x = 0ull; k4[j].y = 0ull; }
            if (act) {
                const ulonglong2* kr = (has_cur && s == scnt - 1)
                    ? (const ulonglong2*)(g_knew + (b * NKV + kv) * HD)
                    : (const ulonglong2*)(kbase + (size_t)(s0 + s) * HD);
#pragma unroll
                for (int j = 0; j < 4; j++) k4[j] = kr[d8 + 8 * j];  // MLP=4
            }
            unsigned long long acc[4] = {0ull, 0ull, 0ull, 0ull};
#pragma unroll
            for (int j = 0; j < 4; j++) {
#pragma unroll
                for (int h = 0; h < 4; h++) {
                    ulonglong2 q2 = ((const ulonglong2*)qsh[h])[d8 + 8 * j];  // LDS.128
                    FMA_F32X2(acc[h], k4[j].x, q2.x, acc[h]);
                    FMA_F32X2(acc[h], k4[j].y, q2.y, acc[h]);
                }
            }
            float r[4];
#pragma unroll
            for (int h = 0; h < 4; h++) {
                float lo, hi;
                asm("mov.b64 {%0, %1}, %2;" : "=f"(lo), "=f"(hi) : "l"(acc[h]));
                r[h] = lo + hi;
            }
            // reduce across the 8 lanes of this row (xor 1,2,4 stays in-group)
#pragma unroll
            for (int o = 1; o <= 4; o <<= 1) {
#pragma unroll
                for (int h = 0; h < 4; h++)
                    r[h] += __shfl_xor_sync(0xffffffffu, r[h], o);
            }
            if (act && d8 == 0)
                sc4[s] = make_float4(r[0] * scale, r[1] * scale,
                                     r[2] * scale, r[3] * scale);
        }
    }
    __syncthreads();

    // ---- softmax, 4 heads in parallel: 64 threads per head ----
    {
        const int h = t >> 6, l64 = t & 63, wid = t >> 5, lane = t & 31;
        const float* schf = (const float*)sc4;  // schf[s*4 + h]
        float lm = -INFINITY;
        for (int s = l64; s < scnt; s += 64) lm = fmaxf(lm, schf[s * 4 + h]);
#pragma unroll
        for (int o = 16; o > 0; o >>= 1) lm = fmaxf(lm, __shfl_xor_sync(0xffffffffu, lm, o));
        if (lane == 0) red[wid] = lm;
        __syncthreads();
        if (l64 == 0) mh[h] = fmaxf(red[2 * h], red[2 * h + 1]);
        __syncthreads();
        const float m = mh[h];
        float ls = 0.f;
        float* scw = (float*)sc4;
        for (int s = l64; s < scnt; s += 64) {
            float p = __expf(scw[s * 4 + h] - m);
            scw[s * 4 + h] = p;
            ls += p;
        }
#pragma unroll
        for (int o = 16; o > 0; o >>= 1) ls += __shfl_xor_sync(0xffffffffu, ls, o);
        if (lane == 0) red[wid] = ls;
        __syncthreads();
        if (l64 == 0) sumh[h] = red[2 * h] + red[2 * h + 1];
    }
    __syncthreads();

    // ---- p @ V: d = t&127, s over 2 halves; f32x2 FMA ----
    {
        const int d = t & 127, half = t >> 7;
        unsigned long long a01 = 0ull, a23 = 0ull;
        const float* vbase = cv + ((size_t)(b * NKV + kv) * KVLEN + s0) * HD + d;
        const int slim = scnt - (has_cur ? 1 : 0);
#pragma unroll 8
        for (int s = half; s < slim; s += 2) {
            float vv = vbase[(size_t)s * HD];
            ulonglong2 p = ((const ulonglong2*)sc4)[s];  // broadcast LDS.128
            unsigned long long v2;
            asm("mov.b64 %0, {%1, %1};" : "=l"(v2) : "f"(vv));
            FMA_F32X2(a01, p.x, v2, a01);
            FMA_F32X2(a23, p.y, v2, a23);
        }
        if (has_cur && ((scnt - 1) & 1) == half) {
            const int s = scnt - 1;
            float vv = g_vnew[(b * NKV + kv) * HD + d];
            ulonglong2 p = ((const ulonglong2*)sc4)[s];
            unsigned long long v2;
            asm("mov.b64 %0, {%1, %1};" : "=l"(v2) : "f"(vv));
            FMA_F32X2(a01, p.x, v2, a01);
            FMA_F32X2(a23, p.y, v2, a23);
        }
        float a0, a1, a2, a3;
        asm("mov.b64 {%0, %1}, %2;" : "=f"(a0), "=f"(a1) : "l"(a01));
        asm("mov.b64 {%0, %1}, %2;" : "=f"(a2), "=f"(a3) : "l"(a23));
        if (half == 1) {
            vred[0][d] = a0; vred[1][d] = a1; vred[2][d] = a2; vred[3][d] = a3;
        }
        __syncthreads();
        if (half == 0) {
            g_pacc[(pbase + 0) * HD + d] = a0 + vred[0][d];
            g_pacc[(pbase + 1) * HD + d] = a1 + vred[1][d];
            g_pacc[(pbase + 2) * HD + d] = a2 + vred[2][d];
            g_pacc[(pbase + 3) * HD + d] = a3 + vred[3][d];
        }
        if (t < GQ) {
            g_pm[pbase + t] = mh[t];
            g_ps[pbase + t] = sumh[t];
        }
    }
}

// ---------------- LSE merge across splits (length-aware, float4) ----------------
__global__ void __launch_bounds__(128) k_combine(const int* __restrict__ curp) {
    const int bk = blockIdx.x;
    const int b = bk >> 3, kv = bk & 7;
    const int t = threadIdx.x;
    const int h = t >> 5, d4 = t & 31;
    const int nsp = (*curp + CHUNK) / CHUNK;  // ceil(L/CHUNK)

    __shared__ float esh[GQ][NSPLIT];
    __shared__ float dens[GQ];
    if (d4 == 0) {
        float m = -INFINITY;
        for (int sp = 0; sp < nsp; sp++)
            m = fmaxf(m, g_pm[(bk * NSPLIT + sp) * GQ + h]);
        float den = 0.f;
        for (int sp = 0; sp < nsp; sp++) {
            float e = __expf(g_pm[(bk * NSPLIT + sp) * GQ + h] - m);
            esh[h][sp] = e;
            den += g_ps[(bk * NSPLIT + sp) * GQ + h] * e;
        }
        dens[h] = den;
    }
    __syncthreads();
    float4 num = make_float4(0.f, 0.f, 0.f, 0.f);
#pragma unroll 4
    for (int sp = 0; sp < nsp; sp++) {
        const float4* pa = (const float4*)(g_pacc + ((bk * NSPLIT + sp) * GQ + h) * HD);
        float4 v = pa[d4];
        float e = esh[h][sp];
        num.x = fmaf(v.x, e, num.x); num.y = fmaf(v.y, e, num.y);
        num.z = fmaf(v.z, e, num.z); num.w = fmaf(v.w, e, num.w);
    }
    const float inv = 1.0f / dens[h];
    float4* o = (float4*)(g_attn + (b * NH + kv * GQ + h) * HD);
    o[d4] = make_float4(num.x * inv, num.y * inv, num.z * inv, num.w * inv);
}

// ---------------- final reduce of out-gemm partials (float4) ----------------
__global__ void __launch_bounds__(256) k_out_reduce(float* __restrict__ out) {
    const int i = blockIdx.x * 256 + threadIdx.x;  // float4 index
    const float4* p2 = (const float4*)g_part2;
    float4 s = make_float4(0.f, 0.f, 0.f, 0.f);
#pragma unroll
    for (int p = 0; p < KSPLIT; p++) {
        float4 v = p2[(size_t)p * (BB * DIM / 4) + i];
        s.x += v.x; s.y += v.y; s.z += v.z; s.w += v.w;
    }
    ((float4*)out)[i] = s;
}

extern "C" void kernel_launch(void* const* d_in, const int* in_sizes, int n_in,
                              void* d_out, int out_size) {
    const float* x    = (const float*)d_in[0];  // attn_norm (1,1,32,4096)
    const float* wqkv = (const float*)d_in[1];  // (4096, 6144)
    const float* wo   = (const float*)d_in[2];  // (4096, 4096)
    const float* rot  = (const float*)d_in[3];  // (128, 128)
    const float* ck   = (const float*)d_in[4];  // (32,8,4096,128)
    const float* cv   = (const float*)d_in[5];  // (32,8,4096,128)
    const int*   curp = (const int*)d_in[6];    // current_pos (low 32 bits)
    float* out = (float*)d_out;

    void *p1, *p2, *attnp;
    cudaGetSymbolAddress(&p1, g_part1);
    cudaGetSymbolAddress(&p2, g_part2);
    cudaGetSymbolAddress(&attnp, g_attn);

    k_gemm_part<QKVC><<<dim3(QKVC / 256, KSPLIT), 256>>>(x, wqkv, (float*)p1);
    k_reduce_rope<<<BB * 48, 128>>>(rot);
    k_dummy<<<1, 32>>>();  // keep k_attn_part in profiled launch slot
    k_attn_part<<<dim3(BB * NKV, NSPLIT), 256>>>(ck, cv, curp);
    k_combine<<<BB * NKV, 128>>>(curp);
    k_gemm_part<DIM><<<dim3(DIM / 256, KSPLIT), 256>>>((const float*)attnp, wo, (float*)p2);
    k_out_reduce<<<BB * DIM / 4 / 256, 256>>>(out);
}